// round 14
// baseline (speedup 1.0000x reference)
#include <cuda_runtime.h>
#include <cuda_fp16.h>
#include <cstdint>
#include <math.h>

// Problem dims
#define NB 512
#define NZ 64
#define NH 256
#define NG 768   // 3*H
#define NT 64
#define NP 10000
#define NPAD 10112          // NP padded to 128
#define MTOT (NB * NT)      // 32768

#define AS_STRIDE 268
#define WS_STRIDE 260
#define GRU_SMEM ((32 * AS_STRIDE + 96 * WS_STRIDE) * 4)

// fp16 GEMM: 128x128 tile, K-tile 32 halfs (64 B/row), 3 stages
// stage = (128 A-rows + 128 B-rows) * 64 B = 16 KB
#define GEMM_SMEM (3 * 16384)

// ---------------- scratch (device globals; no allocations allowed) ----------
__device__ float g_h0[NB * NH];
__device__ float g_g0[NG];
__device__ float g_st0[2][NB * NH];
__device__ float g_st1[2][NB * NH];
__device__ __half g_y0h[MTOT * NH];          // layer0 outputs, fp16, kp32-permuted
__device__ float g_gx1[(size_t)MTOT * NG];
__device__ float g_y1[MTOT * NH];            // layer1 outputs (fp32, pre-LN)
__device__ __half g_acth[MTOT * NH];         // post LN+ELU, fp16, kp32-permuted
__device__ __half g_Wih1h[NG * NH];          // fp16, kp32-permuted
__device__ __half g_Wouth[NPAD * NH];        // fp16, kp32-permuted, zero padded
__device__ unsigned g_cnt2[2][NT][16];       // per-(layer,t,batch-tile) barrier

// ---------------- helpers ----------------------------------------------------
__device__ __forceinline__ float f2tf32(float f) {
    uint32_t u;
    asm("cvt.rna.tf32.f32 %0, %1;" : "=r"(u) : "f"(f));
    return __uint_as_float(u);
}

// fp16 m16n8k16 K-permutation within each 32-block:
// thread c (= (k>>1)&3) gets its 8 halfs {2c,2c+1,2c+8,2c+9, +16...} contiguous.
__device__ __forceinline__ int kp32(int k) {
    return (k & ~31) | (((k >> 1) & 3) << 3) | (((k >> 4) & 1) << 2)
         | (((k >> 3) & 1) << 1) | (k & 1);
}

__device__ __forceinline__ void mma_tf32(float* c, const uint32_t* a, const uint32_t* b) {
    asm volatile(
        "mma.sync.aligned.m16n8k8.row.col.f32.tf32.tf32.f32 "
        "{%0,%1,%2,%3},{%4,%5,%6,%7},{%8,%9},{%0,%1,%2,%3};"
        : "+f"(c[0]), "+f"(c[1]), "+f"(c[2]), "+f"(c[3])
        : "r"(a[0]), "r"(a[1]), "r"(a[2]), "r"(a[3]), "r"(b[0]), "r"(b[1]));
}

__device__ __forceinline__ void mma_f16(float* c, uint32_t a0, uint32_t a1,
                                        uint32_t a2, uint32_t a3,
                                        uint32_t b0, uint32_t b1) {
    asm volatile(
        "mma.sync.aligned.m16n8k16.row.col.f32.f16.f16.f32 "
        "{%0,%1,%2,%3},{%4,%5,%6,%7},{%8,%9},{%0,%1,%2,%3};"
        : "+f"(c[0]), "+f"(c[1]), "+f"(c[2]), "+f"(c[3])
        : "r"(a0), "r"(a1), "r"(a2), "r"(a3), "r"(b0), "r"(b1));
}

__device__ __forceinline__ float sigmoidf_(float x) {
    return 1.f / (1.f + __expf(-x));
}

__device__ __forceinline__ void cp_async16(void* smem_dst, const void* gsrc) {
    unsigned a = (unsigned)__cvta_generic_to_shared(smem_dst);
    asm volatile("cp.async.cg.shared.global [%0], [%1], 16;" :: "r"(a), "l"(gsrc));
}

// ---------------- reset barrier counters -------------------------------------
__global__ void reset_kernel() {
    int i = blockIdx.x * blockDim.x + threadIdx.x;   // 2*64*16 = 2048
    ((unsigned*)g_cnt2)[i] = 0u;
}

// ---------------- prep 1: h0 = ELU(z @ W_init^T + b_init); g0 ---------------
__global__ void prep1_kernel(const float* __restrict__ z,
                             const float* __restrict__ Wi,
                             const float* __restrict__ bi,
                             const float* __restrict__ emb,
                             const float* __restrict__ Wih0,
                             const float* __restrict__ bih0) {
    int blk = blockIdx.x;
    int tid = threadIdx.x;   // 256
    if (blk < NB) {
        __shared__ float zs[NZ];
        if (tid < NZ) zs[tid] = z[blk * NZ + tid];
        __syncthreads();
        float acc = bi[tid];
        #pragma unroll 8
        for (int k = 0; k < NZ; k++) acc = fmaf(zs[k], Wi[tid * NZ + k], acc);
        float h = acc > 0.f ? acc : (expf(acc) - 1.f);
        g_h0[blk * NH + tid] = h;
        g_st0[0][blk * NH + tid] = h;
        g_st1[0][blk * NH + tid] = h;
    } else {
        __shared__ float es[NH];
        es[tid] = emb[tid];
        __syncthreads();
        int g = (blk - NB) * NH + tid;
        float acc = bih0[g];
        #pragma unroll 8
        for (int k = 0; k < NH; k++) acc = fmaf(es[k], Wih0[g * NH + k], acc);
        g_g0[g] = acc;
    }
}

// ---------------- prep: fp16 + kp32-permuted copies of B matrices ------------
__global__ void convw_kernel(const float* __restrict__ Wih1,
                             const float* __restrict__ Wout) {
    int idx = blockIdx.x * blockDim.x + threadIdx.x;
    const int n1 = NG * NH;
    const int n2 = NPAD * NH;
    if (idx < n1) {
        int row = idx >> 8, col = idx & 255;
        g_Wih1h[(row << 8) | kp32(col)] = __float2half_rn(Wih1[idx]);
    }
    for (int j = idx; j < n2; j += gridDim.x * blockDim.x) {
        int row = j >> 8, col = j & 255;
        g_Wouth[(row << 8) | kp32(col)] =
            (row < NP) ? __float2half_rn(Wout[j]) : __float2half_rn(0.f);
    }
}

// ---------------- persistent GRU layer kernel --------------------------------
__global__ __launch_bounds__(256, 1) void gru_persist_kernel(
    int layer, const float* __restrict__ Whh, const float* __restrict__ bhh) {
    extern __shared__ float smem[];
    float* As = smem;
    float* Ws = smem + 32 * AS_STRIDE;

    const int tid = threadIdx.x;
    const int lane = tid & 31;
    const int warp = tid >> 5;
    const int wm = warp & 1;
    const int wn = warp >> 1;
    const int bb0 = blockIdx.x * 32;
    const int hj0 = blockIdx.y * 32;

    float* st[2];
    if (layer) { st[0] = g_st1[0]; st[1] = g_st1[1]; }
    else       { st[0] = g_st0[0]; st[1] = g_st0[1]; }

    #pragma unroll
    for (int i = 0; i < 24; i++) {
        int f = tid + i * 256;
        int rr = f >> 6;
        int c4 = (f & 63) << 2;
        int gate = rr >> 5;
        int r = rr & 31;
        float4 v = *(const float4*)(Whh + (size_t)(gate * NH + hj0 + r) * NH + c4);
        float4 w;
        w.x = f2tf32(v.x); w.y = f2tf32(v.y); w.z = f2tf32(v.z); w.w = f2tf32(v.w);
        *(float4*)(Ws + rr * WS_STRIDE + c4) = w;
    }

    const int r0l = wm * 16 + (lane >> 2);
    const int cl = wn * 8 + (lane & 3) * 2;
    const int jg = hj0 + cl;
    const int pj0 = kp32(jg);                // even; kp32(jg)+1 == kp32(jg+1)

    const float2 br2 = *(const float2*)(bhh + jg);
    const float2 bz2 = *(const float2*)(bhh + NH + jg);
    const float2 bn2 = *(const float2*)(bhh + 2 * NH + jg);
    float2 x0r, x0z, x0n;
    if (!layer) {
        x0r = *(const float2*)(g_g0 + jg);
        x0z = *(const float2*)(g_g0 + NH + jg);
        x0n = *(const float2*)(g_g0 + 2 * NH + jg);
    }

    const float* aBase = As + (size_t)r0l * AS_STRIDE + (lane & 3);
    const float* bBase = Ws + (size_t)(wn * 8 + (lane >> 2)) * WS_STRIDE + (lane & 3);

    __syncthreads();

    for (int t = 0; t < NT; t++) {
        const float* hc = st[t & 1];
        float* hn_out = st[(t + 1) & 1];

        // ---- prefetch x-gates and h_prev (hide L2 behind the MMA chain) ----
        float2 xr[2], xz[2], xn[2], hp[2];
        #pragma unroll
        for (int rr = 0; rr < 2; rr++) {
            int b = bb0 + r0l + rr * 8;
            if (!layer) { xr[rr] = x0r; xz[rr] = x0z; xn[rr] = x0n; }
            else {
                const float* gxp = g_gx1 + ((size_t)b * NT + t) * NG;
                xr[rr] = *(const float2*)(gxp + jg);
                xz[rr] = *(const float2*)(gxp + NH + jg);
                xn[rr] = *(const float2*)(gxp + 2 * NH + jg);
            }
            hp[rr] = __ldcg((const float2*)(hc + (size_t)b * NH + jg));
        }

        // ---- stage h tile (L2-coherent loads), convert to tf32 ----
        #pragma unroll
        for (int i = 0; i < 8; i++) {
            int f = tid + i * 256;
            int row = f >> 6;
            int c4 = (f & 63) << 2;
            float4 v = __ldcg((const float4*)(hc + (size_t)(bb0 + row) * NH + c4));
            float4 w;
            w.x = f2tf32(v.x); w.y = f2tf32(v.y); w.z = f2tf32(v.z); w.w = f2tf32(v.w);
            *(float4*)(As + row * AS_STRIDE + c4) = w;
        }
        __syncthreads();

        float acc[3][4];
        #pragma unroll
        for (int g = 0; g < 3; g++)
            #pragma unroll
            for (int c = 0; c < 4; c++) acc[g][c] = 0.f;

        #pragma unroll 8
        for (int k = 0; k < NH; k += 8) {
            uint32_t a[4], b[2];
            a[0] = __float_as_uint(aBase[k]);
            a[1] = __float_as_uint(aBase[8 * AS_STRIDE + k]);
            a[2] = __float_as_uint(aBase[k + 4]);
            a[3] = __float_as_uint(aBase[8 * AS_STRIDE + k + 4]);
            #pragma unroll
            for (int g = 0; g < 3; g++) {
                b[0] = __float_as_uint(bBase[g * 32 * WS_STRIDE + k]);
                b[1] = __float_as_uint(bBase[g * 32 * WS_STRIDE + k + 4]);
                mma_tf32(acc[g], a, b);
            }
        }

        // ---- gates + state update; store hn first (the only cross-block dep)
        float2 hv[2];
        #pragma unroll
        for (int rr = 0; rr < 2; rr++) {
            int b = bb0 + r0l + rr * 8;
            float r_0 = sigmoidf_(xr[rr].x + acc[0][rr * 2 + 0] + br2.x);
            float r_1 = sigmoidf_(xr[rr].y + acc[0][rr * 2 + 1] + br2.y);
            float u_0 = sigmoidf_(xz[rr].x + acc[1][rr * 2 + 0] + bz2.x);
            float u_1 = sigmoidf_(xz[rr].y + acc[1][rr * 2 + 1] + bz2.y);
            float n_0 = tanhf(xn[rr].x + r_0 * (acc[2][rr * 2 + 0] + bn2.x));
            float n_1 = tanhf(xn[rr].y + r_1 * (acc[2][rr * 2 + 1] + bn2.y));
            hv[rr].x = (1.f - u_0) * n_0 + u_0 * hp[rr].x;
            hv[rr].y = (1.f - u_1) * n_1 + u_1 * hp[rr].y;
            __stcg((float2*)(hn_out + (size_t)b * NH + jg), hv[rr]);
        }

        // arrive as soon as hn stores are fenced; overlap y-store with arrival
        __threadfence();
        __syncthreads();
        if (tid == 0) atomicAdd(&g_cnt2[layer][t][blockIdx.x], 1u);

        #pragma unroll
        for (int rr = 0; rr < 2; rr++) {
            int b = bb0 + r0l + rr * 8;
            if (!layer) {
                __half2 hh = __floats2half2_rn(hv[rr].x, hv[rr].y);
                *(__half2*)(g_y0h + ((size_t)b * NT + t) * NH + pj0) = hh;
            } else {
                *(float2*)(g_y1 + ((size_t)b * NT + t) * NH + jg) = hv[rr];
            }
        }
        __syncthreads();
        if (tid == 0) {
            volatile unsigned* p = &g_cnt2[layer][t][blockIdx.x];
            while (*p < 8u) { }
        }
        __syncthreads();
    }
}

// ---------------- LayerNorm + ELU (fp16, kp32-permuted store) ----------------
__global__ void ln_elu_kernel(const float* __restrict__ gam,
                              const float* __restrict__ bet) {
    int row = blockIdx.x;
    int tid = threadIdx.x;
    float v = g_y1[(size_t)row * NH + tid];

    __shared__ float red[8];
    float s = v;
    #pragma unroll
    for (int o = 16; o; o >>= 1) s += __shfl_xor_sync(0xffffffffu, s, o);
    if ((tid & 31) == 0) red[tid >> 5] = s;
    __syncthreads();
    float tot = red[0] + red[1] + red[2] + red[3] + red[4] + red[5] + red[6] + red[7];
    float mu = tot * (1.f / NH);
    __syncthreads();

    float d = v - mu;
    s = d * d;
    #pragma unroll
    for (int o = 16; o; o >>= 1) s += __shfl_xor_sync(0xffffffffu, s, o);
    if ((tid & 31) == 0) red[tid >> 5] = s;
    __syncthreads();
    tot = red[0] + red[1] + red[2] + red[3] + red[4] + red[5] + red[6] + red[7];
    float var = tot * (1.f / NH);

    float yv = d * rsqrtf(var + 1e-5f) * gam[tid] + bet[tid];
    yv = yv > 0.f ? yv : (__expf(yv) - 1.f);
    g_acth[(size_t)row * NH + kp32(tid)] = __float2half_rn(yv);
}

// ---------------- fp16 128x128 3-stage pipelined GEMM ------------------------
// A: M x 256 halfs (kp32-permuted), B: Npad x 256 halfs (kp32-permuted).
// smem row = 64 B (32 halfs) = 4 x 16B chunks; phys chunk = ck ^ ((row>>1)&3).
// Stage s at smc + s*16384: A 128 rows, B 128 rows.
__global__ __launch_bounds__(256, 2) void gemm_pipe_kernel(
    const __half* __restrict__ A, const __half* __restrict__ Bm,
    const float* __restrict__ bias, float* __restrict__ C, int Nstore) {
    extern __shared__ char smc[];

    const int tid = threadIdx.x;
    const int lane = tid & 31;
    const int warp = tid >> 5;
    const int wm = warp & 1;
    const int wn = warp >> 1;
    const int m0 = blockIdx.y * 128;
    const int n0 = blockIdx.x * 128;

    float acc[4][4][4];
    #pragma unroll
    for (int a = 0; a < 4; a++)
        #pragma unroll
        for (int b = 0; b < 4; b++)
            #pragma unroll
            for (int c = 0; c < 4; c++) acc[a][b][c] = 0.f;

    auto stagef = [&](int kt, int s) {
        const int ko = kt * 32;             // half offset
        char* dA = smc + s * 16384;
        char* dB = dA + 8192;
        #pragma unroll
        for (int i = 0; i < 4; i++) {
            int idx = i * 256 + tid;        // 0..1023
            int r = (idx >> 2) & 127;
            int ck = idx & 3;
            int pc = ck ^ ((r >> 1) & 3);
            if (idx < 512)
                cp_async16(dA + r * 64 + pc * 16, A + (size_t)(m0 + r) * NH + ko + ck * 8);
            else
                cp_async16(dB + r * 64 + pc * 16, Bm + (size_t)(n0 + r) * NH + ko + ck * 8);
        }
        asm volatile("cp.async.commit_group;");
    };

    // prologue: two tiles in flight
    stagef(0, 0);
    stagef(1, 1);

    const int gq = lane >> 2;
    const int c = lane & 3;

    #pragma unroll
    for (int kt = 0; kt < 8; kt++) {
        if (kt < 7) asm volatile("cp.async.wait_group 1;");
        else        asm volatile("cp.async.wait_group 0;");
        __syncthreads();
        if (kt + 2 < 8) stagef(kt + 2, (kt + 2) % 3);

        const char* sAb = smc + (kt % 3) * 16384;
        const char* sBb = sAb + 8192;

        uint4 bv[4];
        #pragma unroll
        for (int nf = 0; nf < 4; nf++) {
            int r = wn * 32 + nf * 8 + gq;
            int pc = c ^ ((r >> 1) & 3);
            bv[nf] = *(const uint4*)(sBb + r * 64 + pc * 16);
        }
        #pragma unroll
        for (int mf = 0; mf < 4; mf++) {
            int r0 = wm * 64 + mf * 16 + gq;
            int pc0 = c ^ ((r0 >> 1) & 3);
            uint4 a0 = *(const uint4*)(sAb + r0 * 64 + pc0 * 16);
            int r1 = r0 + 8;
            int pc1 = c ^ ((r1 >> 1) & 3);
            uint4 a1 = *(const uint4*)(sAb + r1 * 64 + pc1 * 16);
            #pragma unroll
            for (int nf = 0; nf < 4; nf++) {
                mma_f16(acc[mf][nf], a0.x, a1.x, a0.y, a1.y, bv[nf].x, bv[nf].y);
                mma_f16(acc[mf][nf], a0.z, a1.z, a0.w, a1.w, bv[nf].z, bv[nf].w);
            }
        }
    }

    // epilogue: add bias, store (guard col < Nstore)
    __syncthreads();
    #pragma unroll
    for (int mf = 0; mf < 4; mf++) {
        int row = m0 + wm * 64 + mf * 16 + (lane >> 2);
        #pragma unroll
        for (int nf = 0; nf < 4; nf++) {
            int col = n0 + wn * 32 + nf * 8 + (lane & 3) * 2;
            if (col < Nstore) {
                float2 bv = *(const float2*)(bias + col);
                float2 o0 = make_float2(acc[mf][nf][0] + bv.x, acc[mf][nf][1] + bv.y);
                float2 o1 = make_float2(acc[mf][nf][2] + bv.x, acc[mf][nf][3] + bv.y);
                *(float2*)(C + (size_t)row * Nstore + col) = o0;
                *(float2*)(C + (size_t)(row + 8) * Nstore + col) = o1;
            }
        }
    }
}

// ---------------- launch -----------------------------------------------------
extern "C" void kernel_launch(void* const* d_in, const int* in_sizes, int n_in,
                              void* d_out, int out_size) {
    const float* z      = (const float*)d_in[0];
    const float* W_init = (const float*)d_in[1];
    const float* b_init = (const float*)d_in[2];
    const float* emb    = (const float*)d_in[3];
    const float* W_ih0  = (const float*)d_in[4];
    const float* W_hh0  = (const float*)d_in[5];
    const float* b_ih0  = (const float*)d_in[6];
    const float* b_hh0  = (const float*)d_in[7];
    const float* W_ih1  = (const float*)d_in[8];
    const float* W_hh1  = (const float*)d_in[9];
    const float* b_ih1  = (const float*)d_in[10];
    const float* b_hh1  = (const float*)d_in[11];
    const float* ln_g   = (const float*)d_in[12];
    const float* ln_b   = (const float*)d_in[13];
    const float* W_out  = (const float*)d_in[14];
    const float* b_out  = (const float*)d_in[15];
    float* out = (float*)d_out;

    static bool attr_done = false;
    if (!attr_done) {
        cudaFuncSetAttribute(gru_persist_kernel,
                             cudaFuncAttributeMaxDynamicSharedMemorySize, GRU_SMEM);
        cudaFuncSetAttribute(gemm_pipe_kernel,
                             cudaFuncAttributeMaxDynamicSharedMemorySize, GEMM_SMEM);
        attr_done = true;
    }

    __half* Wih1h; cudaGetSymbolAddress((void**)&Wih1h, g_Wih1h);
    __half* Wouth; cudaGetSymbolAddress((void**)&Wouth, g_Wouth);
    __half* y0h;   cudaGetSymbolAddress((void**)&y0h, g_y0h);
    __half* acth;  cudaGetSymbolAddress((void**)&acth, g_acth);
    float* gx1;    cudaGetSymbolAddress((void**)&gx1, g_gx1);

    reset_kernel<<<8, 256>>>();
    prep1_kernel<<<NB + 3, 256>>>(z, W_init, b_init, emb, W_ih0, b_ih0);
    convw_kernel<<<2720, 256>>>(W_ih1, W_out);

    // GRU layer 0 (persistent)
    gru_persist_kernel<<<dim3(16, 8), 256, GRU_SMEM>>>(0, W_hh0, b_hh0);

    // gx1 = Y0 @ W_ih1^T + b_ih1  (fp16 GEMM)
    gemm_pipe_kernel<<<dim3(NG / 128, MTOT / 128), 256, GEMM_SMEM>>>(
        y0h, Wih1h, b_ih1, gx1, NG);

    // GRU layer 1 (persistent)
    gru_persist_kernel<<<dim3(16, 8), 256, GRU_SMEM>>>(1, W_hh1, b_hh1);

    // LayerNorm + ELU
    ln_elu_kernel<<<MTOT, 256>>>(ln_g, ln_b);

    // logits = act @ W_out^T + b_out  (fp16 GEMM)
    gemm_pipe_kernel<<<dim3(NPAD / 128, MTOT / 128), 256, GEMM_SMEM>>>(
        acth, Wouth, b_out, out, NP);
}

// round 15
// speedup vs baseline: 1.1883x; 1.1883x over previous
#include <cuda_runtime.h>
#include <cuda_fp16.h>
#include <cstdint>
#include <math.h>

// Problem dims
#define NB 512
#define NZ 64
#define NH 256
#define NG 768   // 3*H
#define NT 64
#define NP 10000
#define NPAD 10112          // NP padded to 128
#define MTOT (NB * NT)      // 32768

// fp16 GEMM: 128x128 tile, K-tile 32 halfs (64 B/row), 3 stages
#define GEMM_SMEM (3 * 16384)

// GRU: 32 blocks x 16 batches, 512 threads. B chunk = 768 rows x 64 B = 48 KB,
// 3 stages + A tile (8 k-chunks x 16 rows x 64 B = 8 KB)
#define GRU_BCHUNK 49152
#define GRU_SMEM (3 * GRU_BCHUNK + 8192)

// ---------------- scratch (device globals; no allocations allowed) ----------
__device__ float g_h0[NB * NH];
__device__ float g_g0[NG];
__device__ __half g_y0h[MTOT * NH];          // layer0 outputs, fp16, kp32-permuted
__device__ float g_gx1[(size_t)MTOT * NG];
__device__ float g_y1[MTOT * NH];            // layer1 outputs (fp32, pre-LN)
__device__ __half g_acth[MTOT * NH];         // post LN+ELU, fp16, kp32-permuted
__device__ __half g_Wih1h[NG * NH];          // fp16, kp32-permuted
__device__ __half g_Wouth[NPAD * NH];        // fp16, kp32-permuted, zero padded
__device__ __half g_Whh0h[NG * NH];          // fp16, kp32-permuted
__device__ __half g_Whh1h[NG * NH];          // fp16, kp32-permuted

// ---------------- helpers ----------------------------------------------------
// fp16 m16n8k16 K-permutation within each 32-block.
__device__ __forceinline__ int kp32(int k) {
    return (k & ~31) | (((k >> 1) & 3) << 3) | (((k >> 4) & 1) << 2)
         | (((k >> 3) & 1) << 1) | (k & 1);
}

__device__ __forceinline__ void mma_f16(float* c, uint32_t a0, uint32_t a1,
                                        uint32_t a2, uint32_t a3,
                                        uint32_t b0, uint32_t b1) {
    asm volatile(
        "mma.sync.aligned.m16n8k16.row.col.f32.f16.f16.f32 "
        "{%0,%1,%2,%3},{%4,%5,%6,%7},{%8,%9},{%0,%1,%2,%3};"
        : "+f"(c[0]), "+f"(c[1]), "+f"(c[2]), "+f"(c[3])
        : "r"(a0), "r"(a1), "r"(a2), "r"(a3), "r"(b0), "r"(b1));
}

__device__ __forceinline__ float sigmoidf_(float x) {
    return 1.f / (1.f + __expf(-x));
}

__device__ __forceinline__ float tanh_ap(float x) {
    float y;
    asm("tanh.approx.f32 %0, %1;" : "=f"(y) : "f"(x));
    return y;
}

__device__ __forceinline__ void cp_async16(void* smem_dst, const void* gsrc) {
    unsigned a = (unsigned)__cvta_generic_to_shared(smem_dst);
    asm volatile("cp.async.cg.shared.global [%0], [%1], 16;" :: "r"(a), "l"(gsrc));
}

// ---------------- prep 1: h0 = ELU(z @ W_init^T + b_init); g0 ---------------
__global__ void prep1_kernel(const float* __restrict__ z,
                             const float* __restrict__ Wi,
                             const float* __restrict__ bi,
                             const float* __restrict__ emb,
                             const float* __restrict__ Wih0,
                             const float* __restrict__ bih0) {
    int blk = blockIdx.x;
    int tid = threadIdx.x;   // 256
    if (blk < NB) {
        __shared__ float zs[NZ];
        if (tid < NZ) zs[tid] = z[blk * NZ + tid];
        __syncthreads();
        float acc = bi[tid];
        #pragma unroll 8
        for (int k = 0; k < NZ; k++) acc = fmaf(zs[k], Wi[tid * NZ + k], acc);
        float h = acc > 0.f ? acc : (expf(acc) - 1.f);
        g_h0[blk * NH + tid] = h;
    } else {
        __shared__ float es[NH];
        es[tid] = emb[tid];
        __syncthreads();
        int g = (blk - NB) * NH + tid;
        float acc = bih0[g];
        #pragma unroll 8
        for (int k = 0; k < NH; k++) acc = fmaf(es[k], Wih0[g * NH + k], acc);
        g_g0[g] = acc;
    }
}

// ---------------- prep: fp16 + kp32-permuted weight copies -------------------
__global__ void convw_kernel(const float* __restrict__ Wih1,
                             const float* __restrict__ Wout,
                             const float* __restrict__ Whh0,
                             const float* __restrict__ Whh1) {
    int idx = blockIdx.x * blockDim.x + threadIdx.x;
    int stride = gridDim.x * blockDim.x;
    const int n1 = NG * NH;
    const int n2 = NPAD * NH;
    for (int j = idx; j < n1; j += stride) {
        int row = j >> 8, col = j & 255;
        int dst = (row << 8) | kp32(col);
        g_Wih1h[dst] = __float2half_rn(Wih1[j]);
        g_Whh0h[dst] = __float2half_rn(Whh0[j]);
        g_Whh1h[dst] = __float2half_rn(Whh1[j]);
    }
    for (int j = idx; j < n2; j += stride) {
        int row = j >> 8, col = j & 255;
        g_Wouth[(row << 8) | kp32(col)] =
            (row < NP) ? __float2half_rn(Wout[j]) : __float2half_rn(0.f);
    }
}

// ---------------- barrier-free GRU: block owns 16 batches x full hidden ------
// 32 blocks, 512 threads (16 warps). Warp w owns hidden cols [w*16, w*16+16)
// for all 3 gates -> gate math register-local. fp32 state carried in regs;
// fp16 copy in smem A-tile feeds the mma. W_hh streamed fp16 from L2 each
// step through a 3-stage cp.async pipeline (48 KB chunks).
template <int LAYER>
__global__ __launch_bounds__(512, 1) void gru_kernel(
    const __half* __restrict__ Wh, const float* __restrict__ bhh) {
    extern __shared__ char smb[];
    char* Bbuf = smb;                         // 3 x 49152
    char* Atile = smb + 3 * GRU_BCHUNK;       // 8192: [kc][16 rows][64 B]

    const int tid = threadIdx.x;
    const int lane = tid & 31;
    const int warp = tid >> 5;
    const int gq = lane >> 2;
    const int c = lane & 3;
    const int bb0 = blockIdx.x * 16;
    const int jbase = warp * 16;

    // store h (fp16) into the A tile at (row r, logical col j), j even
    auto storeA = [&](int r, int j, __half2 v) {
        int kc = j >> 5;
        int p = kp32(j) & 31;
        int pc = (p >> 3) ^ ((r >> 1) & 3);
        *(__half2*)(Atile + kc * 1024 + r * 64 + pc * 16 + (p & 7) * 2) = v;
    };

    // constants
    float2 bs[3][2], x0[3][2];
    #pragma unroll
    for (int g = 0; g < 3; g++)
        #pragma unroll
        for (int nf = 0; nf < 2; nf++) {
            int col = jbase + nf * 8 + c * 2;
            bs[g][nf] = *(const float2*)(bhh + g * NH + col);
            if (LAYER == 0) x0[g][nf] = *(const float2*)(g_g0 + g * NH + col);
        }

    // initial state: regs + A tile
    float hprev[2][4];
    #pragma unroll
    for (int nf = 0; nf < 2; nf++) {
        int col = jbase + nf * 8 + c * 2;
        #pragma unroll
        for (int h2 = 0; h2 < 2; h2++) {
            float2 v = *(const float2*)(g_h0 + (size_t)(bb0 + gq + 8 * h2) * NH + col);
            hprev[nf][h2 * 2 + 0] = v.x;
            hprev[nf][h2 * 2 + 1] = v.y;
            storeA(gq + 8 * h2, col, __floats2half2_rn(v.x, v.y));
        }
    }
    __syncthreads();

    // stage W chunk kc (rows 0..767 x 32 halfs) into buffer buf
    auto stageB = [&](int kc, int buf) {
        char* dst = Bbuf + buf * GRU_BCHUNK;
        const __half* src = Wh + kc * 32;
        #pragma unroll
        for (int i = 0; i < 6; i++) {
            int idx = i * 512 + tid;           // 0..3071
            int r = idx >> 2, ck = idx & 3;
            int pc = ck ^ ((r >> 1) & 3);
            cp_async16(dst + r * 64 + pc * 16, src + (size_t)r * NH + ck * 8);
        }
        asm volatile("cp.async.commit_group;");
    };

    int cc = 0;
    stageB(0, 0);
    stageB(1, 1);

    const int pcA = c ^ ((gq >> 1) & 3);

    for (int t = 0; t < NT; t++) {
        // prefetch layer-1 input gates for this step (L2; hidden under mma)
        float2 xg[2][3][2];
        if (LAYER == 1) {
            #pragma unroll
            for (int h2 = 0; h2 < 2; h2++) {
                const float* base = g_gx1 + ((size_t)(bb0 + gq + 8 * h2) * NT + t) * NG;
                #pragma unroll
                for (int g = 0; g < 3; g++)
                    #pragma unroll
                    for (int nf = 0; nf < 2; nf++)
                        xg[h2][g][nf] = *(const float2*)(base + g * NH + jbase + nf * 8 + c * 2);
            }
        }

        float acc[3][2][4];
        #pragma unroll
        for (int g = 0; g < 3; g++)
            #pragma unroll
            for (int nf = 0; nf < 2; nf++)
                #pragma unroll
                for (int q = 0; q < 4; q++) acc[g][nf][q] = 0.f;

        #pragma unroll
        for (int kc = 0; kc < 8; kc++) {
            if (kc < 7) asm volatile("cp.async.wait_group 1;");
            else        asm volatile("cp.async.wait_group 0;");
            __syncthreads();
            if (kc + 2 < 8) stageB(kc + 2, (cc + 2) % 3);

            const char* Ab = Atile + kc * 1024;
            uint4 a0 = *(const uint4*)(Ab + gq * 64 + pcA * 16);
            uint4 a1 = *(const uint4*)(Ab + (gq + 8) * 64 + pcA * 16);
            const char* Bb = Bbuf + (cc % 3) * GRU_BCHUNK;
            #pragma unroll
            for (int g = 0; g < 3; g++)
                #pragma unroll
                for (int nf = 0; nf < 2; nf++) {
                    int rB = g * NH + jbase + nf * 8 + gq;
                    uint4 bv = *(const uint4*)(Bb + rB * 64 + (c ^ ((rB >> 1) & 3)) * 16);
                    mma_f16(acc[g][nf], a0.x, a1.x, a0.y, a1.y, bv.x, bv.y);
                    mma_f16(acc[g][nf], a0.z, a1.z, a0.w, a1.w, bv.z, bv.w);
                }
            cc++;
        }

        // stage next step's chunks 0,1 (same weights) while gates compute
        if (t + 1 < NT) {
            stageB(0, cc % 3);
            stageB(1, (cc + 1) % 3);
        }

        // gates + state update (register-local)
        #pragma unroll
        for (int nf = 0; nf < 2; nf++) {
            int col = jbase + nf * 8 + c * 2;
            #pragma unroll
            for (int h2 = 0; h2 < 2; h2++) {
                int b = bb0 + gq + 8 * h2;
                float2 xr = (LAYER == 1) ? xg[h2][0][nf] : x0[0][nf];
                float2 xz = (LAYER == 1) ? xg[h2][1][nf] : x0[1][nf];
                float2 xn = (LAYER == 1) ? xg[h2][2][nf] : x0[2][nf];
                float r0 = sigmoidf_(xr.x + acc[0][nf][h2 * 2 + 0] + bs[0][nf].x);
                float r1 = sigmoidf_(xr.y + acc[0][nf][h2 * 2 + 1] + bs[0][nf].y);
                float u0 = sigmoidf_(xz.x + acc[1][nf][h2 * 2 + 0] + bs[1][nf].x);
                float u1 = sigmoidf_(xz.y + acc[1][nf][h2 * 2 + 1] + bs[1][nf].y);
                float n0 = tanh_ap(xn.x + r0 * (acc[2][nf][h2 * 2 + 0] + bs[2][nf].x));
                float n1 = tanh_ap(xn.y + r1 * (acc[2][nf][h2 * 2 + 1] + bs[2][nf].y));
                float h0 = (1.f - u0) * n0 + u0 * hprev[nf][h2 * 2 + 0];
                float h1 = (1.f - u1) * n1 + u1 * hprev[nf][h2 * 2 + 1];
                hprev[nf][h2 * 2 + 0] = h0;
                hprev[nf][h2 * 2 + 1] = h1;
                if (LAYER == 0) {
                    *(__half2*)(g_y0h + ((size_t)b * NT + t) * NH + kp32(col)) =
                        __floats2half2_rn(h0, h1);
                } else {
                    float2 o; o.x = h0; o.y = h1;
                    *(float2*)(g_y1 + ((size_t)b * NT + t) * NH + col) = o;
                }
            }
        }

        // all warps done reading the A tile (chunk syncs) -> safe to rewrite
        __syncthreads();
        #pragma unroll
        for (int nf = 0; nf < 2; nf++) {
            int col = jbase + nf * 8 + c * 2;
            #pragma unroll
            for (int h2 = 0; h2 < 2; h2++)
                storeA(gq + 8 * h2, col,
                       __floats2half2_rn(hprev[nf][h2 * 2 + 0], hprev[nf][h2 * 2 + 1]));
        }
        // next iteration's first chunk-sync orders these writes vs reads
    }
}

// ---------------- LayerNorm + ELU (fp16, kp32-permuted store) ----------------
__global__ void ln_elu_kernel(const float* __restrict__ gam,
                              const float* __restrict__ bet) {
    int row = blockIdx.x;
    int tid = threadIdx.x;
    float v = g_y1[(size_t)row * NH + tid];

    __shared__ float red[8];
    float s = v;
    #pragma unroll
    for (int o = 16; o; o >>= 1) s += __shfl_xor_sync(0xffffffffu, s, o);
    if ((tid & 31) == 0) red[tid >> 5] = s;
    __syncthreads();
    float tot = red[0] + red[1] + red[2] + red[3] + red[4] + red[5] + red[6] + red[7];
    float mu = tot * (1.f / NH);
    __syncthreads();

    float d = v - mu;
    s = d * d;
    #pragma unroll
    for (int o = 16; o; o >>= 1) s += __shfl_xor_sync(0xffffffffu, s, o);
    if ((tid & 31) == 0) red[tid >> 5] = s;
    __syncthreads();
    tot = red[0] + red[1] + red[2] + red[3] + red[4] + red[5] + red[6] + red[7];
    float var = tot * (1.f / NH);

    float yv = d * rsqrtf(var + 1e-5f) * gam[tid] + bet[tid];
    yv = yv > 0.f ? yv : (__expf(yv) - 1.f);
    g_acth[(size_t)row * NH + kp32(tid)] = __float2half_rn(yv);
}

// ---------------- fp16 128x128 3-stage pipelined GEMM ------------------------
__global__ __launch_bounds__(256, 2) void gemm_pipe_kernel(
    const __half* __restrict__ A, const __half* __restrict__ Bm,
    const float* __restrict__ bias, float* __restrict__ C, int Nstore) {
    extern __shared__ char smc[];

    const int tid = threadIdx.x;
    const int lane = tid & 31;
    const int warp = tid >> 5;
    const int wm = warp & 1;
    const int wn = warp >> 1;
    const int m0 = blockIdx.y * 128;
    const int n0 = blockIdx.x * 128;

    float acc[4][4][4];
    #pragma unroll
    for (int a = 0; a < 4; a++)
        #pragma unroll
        for (int b = 0; b < 4; b++)
            #pragma unroll
            for (int c = 0; c < 4; c++) acc[a][b][c] = 0.f;

    auto stagef = [&](int kt, int s) {
        const int ko = kt * 32;
        char* dA = smc + s * 16384;
        char* dB = dA + 8192;
        #pragma unroll
        for (int i = 0; i < 4; i++) {
            int idx = i * 256 + tid;
            int r = (idx >> 2) & 127;
            int ck = idx & 3;
            int pc = ck ^ ((r >> 1) & 3);
            if (idx < 512)
                cp_async16(dA + r * 64 + pc * 16, A + (size_t)(m0 + r) * NH + ko + ck * 8);
            else
                cp_async16(dB + r * 64 + pc * 16, Bm + (size_t)(n0 + r) * NH + ko + ck * 8);
        }
        asm volatile("cp.async.commit_group;");
    };

    stagef(0, 0);
    stagef(1, 1);

    const int gq = lane >> 2;
    const int c = lane & 3;

    #pragma unroll
    for (int kt = 0; kt < 8; kt++) {
        if (kt < 7) asm volatile("cp.async.wait_group 1;");
        else        asm volatile("cp.async.wait_group 0;");
        __syncthreads();
        if (kt + 2 < 8) stagef(kt + 2, (kt + 2) % 3);

        const char* sAb = smc + (kt % 3) * 16384;
        const char* sBb = sAb + 8192;

        uint4 bv[4];
        #pragma unroll
        for (int nf = 0; nf < 4; nf++) {
            int r = wn * 32 + nf * 8 + gq;
            int pc = c ^ ((r >> 1) & 3);
            bv[nf] = *(const uint4*)(sBb + r * 64 + pc * 16);
        }
        #pragma unroll
        for (int mf = 0; mf < 4; mf++) {
            int r0 = wm * 64 + mf * 16 + gq;
            int pc0 = c ^ ((r0 >> 1) & 3);
            uint4 a0 = *(const uint4*)(sAb + r0 * 64 + pc0 * 16);
            uint4 a1 = *(const uint4*)(sAb + (r0 + 8) * 64 + pc0 * 16);
            #pragma unroll
            for (int nf = 0; nf < 4; nf++) {
                mma_f16(acc[mf][nf], a0.x, a1.x, a0.y, a1.y, bv[nf].x, bv[nf].y);
                mma_f16(acc[mf][nf], a0.z, a1.z, a0.w, a1.w, bv[nf].z, bv[nf].w);
            }
        }
    }

    __syncthreads();
    #pragma unroll
    for (int mf = 0; mf < 4; mf++) {
        int row = m0 + wm * 64 + mf * 16 + (lane >> 2);
        #pragma unroll
        for (int nf = 0; nf < 4; nf++) {
            int col = n0 + wn * 32 + nf * 8 + (lane & 3) * 2;
            if (col < Nstore) {
                float2 bv2 = *(const float2*)(bias + col);
                float2 o0 = make_float2(acc[mf][nf][0] + bv2.x, acc[mf][nf][1] + bv2.y);
                float2 o1 = make_float2(acc[mf][nf][2] + bv2.x, acc[mf][nf][3] + bv2.y);
                *(float2*)(C + (size_t)row * Nstore + col) = o0;
                *(float2*)(C + (size_t)(row + 8) * Nstore + col) = o1;
            }
        }
    }
}

// ---------------- launch -----------------------------------------------------
extern "C" void kernel_launch(void* const* d_in, const int* in_sizes, int n_in,
                              void* d_out, int out_size) {
    const float* z      = (const float*)d_in[0];
    const float* W_init = (const float*)d_in[1];
    const float* b_init = (const float*)d_in[2];
    const float* emb    = (const float*)d_in[3];
    const float* W_ih0  = (const float*)d_in[4];
    const float* W_hh0  = (const float*)d_in[5];
    const float* b_ih0  = (const float*)d_in[6];
    const float* b_hh0  = (const float*)d_in[7];
    const float* W_ih1  = (const float*)d_in[8];
    const float* W_hh1  = (const float*)d_in[9];
    const float* b_ih1  = (const float*)d_in[10];
    const float* b_hh1  = (const float*)d_in[11];
    const float* ln_g   = (const float*)d_in[12];
    const float* ln_b   = (const float*)d_in[13];
    const float* W_out  = (const float*)d_in[14];
    const float* b_out  = (const float*)d_in[15];
    float* out = (float*)d_out;

    static bool attr_done = false;
    if (!attr_done) {
        cudaFuncSetAttribute(gru_kernel<0>,
                             cudaFuncAttributeMaxDynamicSharedMemorySize, GRU_SMEM);
        cudaFuncSetAttribute(gru_kernel<1>,
                             cudaFuncAttributeMaxDynamicSharedMemorySize, GRU_SMEM);
        cudaFuncSetAttribute(gemm_pipe_kernel,
                             cudaFuncAttributeMaxDynamicSharedMemorySize, GEMM_SMEM);
        attr_done = true;
    }

    __half* Wih1h; cudaGetSymbolAddress((void**)&Wih1h, g_Wih1h);
    __half* Wouth; cudaGetSymbolAddress((void**)&Wouth, g_Wouth);
    __half* Whh0h; cudaGetSymbolAddress((void**)&Whh0h, g_Whh0h);
    __half* Whh1h; cudaGetSymbolAddress((void**)&Whh1h, g_Whh1h);
    __half* y0h;   cudaGetSymbolAddress((void**)&y0h, g_y0h);
    __half* acth;  cudaGetSymbolAddress((void**)&acth, g_acth);
    float* gx1;    cudaGetSymbolAddress((void**)&gx1, g_gx1);

    prep1_kernel<<<NB + 3, 256>>>(z, W_init, b_init, emb, W_ih0, b_ih0);
    convw_kernel<<<2720, 256>>>(W_ih1, W_out, W_hh0, W_hh1);

    // GRU layer 0 (barrier-free)
    gru_kernel<0><<<32, 512, GRU_SMEM>>>(Whh0h, b_hh0);

    // gx1 = Y0 @ W_ih1^T + b_ih1  (fp16 GEMM)
    gemm_pipe_kernel<<<dim3(NG / 128, MTOT / 128), 256, GEMM_SMEM>>>(
        y0h, Wih1h, b_ih1, gx1, NG);

    // GRU layer 1 (barrier-free)
    gru_kernel<1><<<32, 512, GRU_SMEM>>>(Whh1h, b_hh1);

    // LayerNorm + ELU
    ln_elu_kernel<<<MTOT, 256>>>(ln_g, ln_b);

    // logits = act @ W_out^T + b_out  (fp16 GEMM)
    gemm_pipe_kernel<<<dim3(NPAD / 128, MTOT / 128), 256, GEMM_SMEM>>>(
        acth, Wouth, b_out, out, NP);
}